// round 14
// baseline (speedup 1.0000x reference)
#include <cuda_runtime.h>
#include <cuda_fp16.h>
#include <cstdint>

#define N_NODES 100000
#define N_EDGES 1600000
#define IN_DIM 128
#define OUT_DIM 64
#define NEG 0.2f
#define EPSV 1e-8f

// ---------------- scratch (device globals: allocation-free) ----------------
__device__ float  g_Qr[(size_t)N_NODES * 256];   // leaky(Q) fp32, [node][h*64+d]
__device__ __half g_Kh[(size_t)N_NODES * 256];   // leaky(K) fp16
__device__ __half g_Hh[(size_t)N_NODES * 256];   // H + bias, fp16
__device__ __half g_xh[(size_t)N_NODES * 128];   // x in fp16
__device__ __half g_Wh[(size_t)3 * 256 * 128];   // W in fp16, [mtx][n][k]
__device__ float  g_e [(size_t)N_EDGES * 4];     // exp(score), [edge][head]
__device__ float  g_zinv[(size_t)N_NODES * 4];   // 1/(z+eps), [node][head]
__device__ int    g_ecol[N_EDGES];
__device__ int    g_deg [N_NODES];
__device__ int    g_rowptr[N_NODES + 1];
__device__ int    g_cursor[N_NODES];
__device__ int    g_bsum[128];
__device__ int    g_boff[128];
__device__ int    g_is64;

// ---------------- helpers ----------------
__device__ __forceinline__ void mma_f16(float* d, const uint32_t* a, uint32_t b0, uint32_t b1) {
    asm volatile(
        "mma.sync.aligned.m16n8k16.row.col.f32.f16.f16.f32 "
        "{%0,%1,%2,%3}, {%4,%5,%6,%7}, {%8,%9}, {%0,%1,%2,%3};"
        : "+f"(d[0]), "+f"(d[1]), "+f"(d[2]), "+f"(d[3])
        : "r"(a[0]), "r"(a[1]), "r"(a[2]), "r"(a[3]), "r"(b0), "r"(b1));
}
__device__ __forceinline__ void ldm4(uint32_t* r, uint32_t addr) {
    asm volatile("ldmatrix.sync.aligned.m8n8.x4.shared.b16 {%0,%1,%2,%3}, [%4];"
                 : "=r"(r[0]), "=r"(r[1]), "=r"(r[2]), "=r"(r[3]) : "r"(addr));
}
__device__ __forceinline__ void cp16(uint32_t smem_addr, const void* gptr, int srcsize) {
    asm volatile("cp.async.cg.shared.global [%0], [%1], 16, %2;"
                 :: "r"(smem_addr), "l"(gptr), "r"(srcsize) : "memory");
}

// ---------------- dtype detection (int64 vs silently-int32 edge_index) -----
__global__ void gat_detect(const void* __restrict__ ei, int E) {
    if (threadIdx.x == 0 && blockIdx.x == 0) {
        const long long* p = (const long long*)ei;
        const int stride = E / 16;
        int ok = 1;
        #pragma unroll
        for (int i = 0; i < 16; i++) {
            long long v = p[(size_t)i * stride];
            if (v < 0 || v >= (long long)N_NODES) ok = 0;
        }
        g_is64 = ok;
    }
}

__device__ __forceinline__ int load_idx(const void* __restrict__ ei, int pos) {
    if (g_is64) return (int)((const long long*)ei)[pos];
    return ((const int*)ei)[pos];
}

// ---------------- fp16 conversions (+ fused deg zero) ----------------
__global__ void gat_xh(const float* __restrict__ x, int total2, int n) {
    const int i = blockIdx.x * blockDim.x + threadIdx.x;   // handles 2 floats
    if (i < total2) {
        const float2 v = *(const float2*)(x + (size_t)i * 2);
        *(__half2*)(g_xh + (size_t)i * 2) = __floats2half2_rn(v.x, v.y);
    }
    if (i < n) g_deg[i] = 0;
}
__global__ void gat_wh(const float* __restrict__ Wq, const float* __restrict__ Wk,
                       const float* __restrict__ Wh) {
    const float* __restrict__ W = (blockIdx.x == 0) ? Wq : ((blockIdx.x == 1) ? Wk : Wh);
    __half* __restrict__ dst = g_Wh + (size_t)blockIdx.x * 256 * 128;
    for (int i = threadIdx.x; i < 256 * 128 / 2; i += blockDim.x) {
        const float2 v = *(const float2*)(W + (size_t)i * 2);
        *(__half2*)(dst + (size_t)i * 2) = __floats2half2_rn(v.x, v.y);
    }
}

// ---------------- fp16 mma GEMM (CTA 128x256, warp tile 32x64, 512 thr) ----
// gridDim = (ceil(n/128), 4): y<3 -> GEMM matrix y; y==3 -> deg count.
// 16 warps in 4x4: wr=(wid>>2)*32, wc=(wid&3)*64. Single K-chunk, cp.async.
// LDH=136 halves (272 B row stride, ≡16 mod 128) -> ldmatrix conflict-free.
// Halves B L2 refill per output row vs BM=64 (one 64 KB W fill per 128 rows).
#define BM 128
#define NT 512
#define LDH 136
#define GEMM_SMEM ((BM + 256) * LDH * 2)   // 104448 B

__global__ __launch_bounds__(NT, 1) void gat_gemm(
    const float* __restrict__ bh, const void* __restrict__ ei, int E, int n)
{
    if (blockIdx.y == 3) {
        const int stride = gridDim.x * NT;
        for (int e = blockIdx.x * NT + threadIdx.x; e < E; e += stride)
            atomicAdd(&g_deg[load_idx(ei, e)], 1);
        return;
    }

    extern __shared__ __half smem[];
    __half* As = smem;                 // BM x LDH
    __half* Bs = smem + BM * LDH;      // 256 x LDH

    const int tid  = threadIdx.x;
    const int wid  = tid >> 5;
    const int lane = tid & 31;
    const int m0   = blockIdx.x * BM;
    const int mtx  = blockIdx.y;                 // 0=Q, 1=K, 2=H
    const __half* __restrict__ Wp = g_Wh + (size_t)mtx * 256 * 128;

    const int wr = (wid >> 2) * 32;              // warp row base (0..96)
    const int wc = (wid & 3) * 64;               // warp col base (0..192)
    const int lr = lane >> 2;
    const int lc = lane & 3;

    const int sel = lane >> 3;
    const int rL  = (sel & 1) * 8 + (lane & 7);
    const int cL  = (sel >> 1) * 8;

    const uint32_t aBase = (uint32_t)__cvta_generic_to_shared(As);
    const uint32_t bBase = (uint32_t)__cvta_generic_to_shared(Bs);

    // fill A: 128 rows x 128 halves = 2048 16B-chunks; 4 per thread (cp.async)
    #pragma unroll
    for (int i = tid; i < 2048; i += NT) {
        const int row = i >> 4;                  // 16 chunks per row
        const int seg = (i & 15) * 8;            // halves
        const int grow = m0 + row;
        const int ok = (grow < n);
        const __half* gp = g_xh + (size_t)(ok ? grow : 0) * 128 + seg;
        cp16(aBase + (row * LDH + seg) * 2, gp, ok ? 16 : 0);   // srcsize 0 -> zero fill
    }
    // fill B: 256 rows x 128 halves = 4096 chunks; 8 per thread
    #pragma unroll
    for (int i = tid; i < 4096; i += NT) {
        const int row = i >> 4;
        const int seg = (i & 15) * 8;
        cp16(bBase + (row * LDH + seg) * 2, Wp + (size_t)row * 128 + seg, 16);
    }
    asm volatile("cp.async.commit_group;" ::: "memory");
    asm volatile("cp.async.wait_group 0;" ::: "memory");
    __syncthreads();

    uint32_t aAddr[2], bAddr[4];
    #pragma unroll
    for (int i = 0; i < 2; i++)
        aAddr[i] = aBase + ((wr + i * 16 + rL) * LDH + cL) * 2;
    #pragma unroll
    for (int j2 = 0; j2 < 4; j2++)
        bAddr[j2] = bBase + ((wc + j2 * 16 + rL) * LDH + cL) * 2;

    float acc[2][8][4];
    #pragma unroll
    for (int i = 0; i < 2; i++)
        #pragma unroll
        for (int j = 0; j < 8; j++)
            #pragma unroll
            for (int t = 0; t < 4; t++) acc[i][j][t] = 0.f;

    #pragma unroll
    for (int ks = 0; ks < 8; ks++) {
        const uint32_t ko = ks * 32;             // 16 halves = 32 B per k-step
        uint32_t a[2][4];
        ldm4(a[0], aAddr[0] + ko);
        ldm4(a[1], aAddr[1] + ko);
        #pragma unroll
        for (int j2 = 0; j2 < 4; j2++) {
            uint32_t b[4];
            ldm4(b, bAddr[j2] + ko);
            mma_f16(acc[0][2 * j2],     a[0], b[0], b[2]);
            mma_f16(acc[1][2 * j2],     a[1], b[0], b[2]);
            mma_f16(acc[0][2 * j2 + 1], a[0], b[1], b[3]);
            mma_f16(acc[1][2 * j2 + 1], a[1], b[1], b[3]);
        }
    }

    // epilogue: Q -> fp32 + leaky; K -> fp16 + leaky; H -> fp16 + bias
    #pragma unroll
    for (int i = 0; i < 2; i++) {
        const int r0 = m0 + wr + i * 16 + lr;
        const int r1 = r0 + 8;
        #pragma unroll
        for (int j = 0; j < 8; j++) {
            const int col = wc + j * 8 + lc * 2;
            float2 v0 = make_float2(acc[i][j][0], acc[i][j][1]);
            float2 v1 = make_float2(acc[i][j][2], acc[i][j][3]);
            if (mtx < 2) {
                v0.x = v0.x > 0.f ? v0.x : NEG * v0.x;
                v0.y = v0.y > 0.f ? v0.y : NEG * v0.y;
                v1.x = v1.x > 0.f ? v1.x : NEG * v1.x;
                v1.y = v1.y > 0.f ? v1.y : NEG * v1.y;
            } else {
                const float bx = bh[col], by = bh[col + 1];
                v0.x += bx; v0.y += by;
                v1.x += bx; v1.y += by;
            }
            if (mtx == 0) {
                if (r0 < n) *(float2*)(g_Qr + (size_t)r0 * 256 + col) = v0;
                if (r1 < n) *(float2*)(g_Qr + (size_t)r1 * 256 + col) = v1;
            } else {
                __half* __restrict__ dsth = (mtx == 1) ? g_Kh : g_Hh;
                if (r0 < n) *(__half2*)(dsth + (size_t)r0 * 256 + col) = __floats2half2_rn(v0.x, v0.y);
                if (r1 < n) *(__half2*)(dsth + (size_t)r1 * 256 + col) = __floats2half2_rn(v1.x, v1.y);
            }
        }
    }
}

// ---------------- CSR build ----------------
__global__ void gat_scan1(int n) {
    __shared__ int warpsum[32];
    const int tid  = threadIdx.x;
    const int lane = tid & 31;
    const int wid  = tid >> 5;
    const int i = blockIdx.x * 1024 + tid;
    const int v = (i < n) ? g_deg[i] : 0;
    int s = v;
    #pragma unroll
    for (int off = 1; off < 32; off <<= 1) {
        int t = __shfl_up_sync(0xFFFFFFFFu, s, off);
        if (lane >= off) s += t;
    }
    if (lane == 31) warpsum[wid] = s;
    __syncthreads();
    if (wid == 0) {
        int w = warpsum[lane];
        #pragma unroll
        for (int off = 1; off < 32; off <<= 1) {
            int t = __shfl_up_sync(0xFFFFFFFFu, w, off);
            if (lane >= off) w += t;
        }
        warpsum[lane] = w;
    }
    __syncthreads();
    const int wbase = (wid == 0) ? 0 : warpsum[wid - 1];
    if (i < n) g_rowptr[i] = wbase + s - v;
    if (tid == 1023) g_bsum[blockIdx.x] = warpsum[31];
}

__global__ void gat_scan2(int nb, int n) {
    const int tid  = threadIdx.x;   // 128 threads
    const int lane = tid & 31;
    const int wid  = tid >> 5;
    __shared__ int warpsum[4];
    const int v = (tid < nb) ? g_bsum[tid] : 0;
    int s = v;
    #pragma unroll
    for (int off = 1; off < 32; off <<= 1) {
        int t = __shfl_up_sync(0xFFFFFFFFu, s, off);
        if (lane >= off) s += t;
    }
    if (lane == 31) warpsum[wid] = s;
    __syncthreads();
    int wbase = 0;
    #pragma unroll
    for (int w = 0; w < 4; w++) if (w < wid) wbase += warpsum[w];
    if (tid < nb) g_boff[tid] = wbase + s - v;
    if (tid == 127) g_rowptr[n] = wbase + s;
}

__global__ void gat_scan3(int n) {
    const int i = blockIdx.x * blockDim.x + threadIdx.x;
    if (i < n) {
        const int r = g_rowptr[i] + g_boff[blockIdx.x >> 2];
        g_rowptr[i] = r;
        g_cursor[i] = r;
    }
}

__global__ void gat_scatter(const void* __restrict__ ei, int E) {
    int e = blockIdx.x * blockDim.x + threadIdx.x;
    if (e < E) {
        int r = load_idx(ei, e);
        int c = load_idx(ei, E + e);
        int p = atomicAdd(&g_cursor[r], 1);
        g_ecol[p] = c;
    }
}

// ---------------- score pass (warp per node): e + zinv ----------------
// K row = 512 bytes fp16. lane l loads uint4 (8 halves) at byte offset l*16.
// head h = l>>3, slot t = l&7 covers dims t*8..t*8+7.
__global__ __launch_bounds__(256) void gat_score(int n) {
    const int warp = (blockIdx.x * blockDim.x + threadIdx.x) >> 5;
    const int lane = threadIdx.x & 31;
    if (warp >= n) return;
    const int u = warp;
    const int h = lane >> 3;
    const int t = lane & 7;
    const int p0 = g_rowptr[u], p1 = g_rowptr[u + 1];

    float qv[8];
    {
        const float4* qp = (const float4*)(g_Qr + (size_t)u * 256 + h * 64 + t * 8);
        float4 a = qp[0], b = qp[1];
        qv[0] = a.x; qv[1] = a.y; qv[2] = a.z; qv[3] = a.w;
        qv[4] = b.x; qv[5] = b.y; qv[6] = b.z; qv[7] = b.w;
    }

    float z = 0.f;
    for (int p = p0; p < p1; p++) {
        const int v = g_ecol[p];
        const uint4 kv = *(const uint4*)((const char*)g_Kh + (size_t)v * 512 + lane * 16);
        const float2 k0 = __half22float2(*(const __half2*)&kv.x);
        const float2 k1 = __half22float2(*(const __half2*)&kv.y);
        const float2 k2 = __half22float2(*(const __half2*)&kv.z);
        const float2 k3 = __half22float2(*(const __half2*)&kv.w);
        float s = qv[0] * k0.x + qv[1] * k0.y + qv[2] * k1.x + qv[3] * k1.y
                + qv[4] * k2.x + qv[5] * k2.y + qv[6] * k3.x + qv[7] * k3.y;
        s += __shfl_xor_sync(0xFFFFFFFFu, s, 4);
        s += __shfl_xor_sync(0xFFFFFFFFu, s, 2);
        s += __shfl_xor_sync(0xFFFFFFFFu, s, 1);
        const float e = __expf(s * 0.125f);
        z += e;
        if (t == 0) g_e[4 * (size_t)p + h] = e;
    }
    if (t == 0) g_zinv[4 * (size_t)u + h] = 1.0f / (z + EPSV);
}

// ---------------- aggregate pass (warp per node), fp16 H ----------------
// lane l handles out dims 2l, 2l+1: head h at half2 index h*32 + l of the row.
__global__ __launch_bounds__(256) void gat_aggr(float* __restrict__ out, int n) {
    const int warp = (blockIdx.x * blockDim.x + threadIdx.x) >> 5;
    const int lane = threadIdx.x & 31;
    if (warp >= n) return;
    const int u = warp;
    const int p0 = g_rowptr[u], p1 = g_rowptr[u + 1];

    const float4 zv = *(const float4*)(g_zinv + 4 * (size_t)u);
    const float i0 = zv.x, i1 = zv.y, i2 = zv.z, i3 = zv.w;

    float ax = 0.f, ay = 0.f;
    for (int p = p0; p < p1; p++) {
        const int v = g_ecol[p];
        const float4 ev = *(const float4*)(g_e + 4 * (size_t)p);
        const float a0 = ev.x * i0, a1 = ev.y * i1, a2 = ev.z * i2, a3 = ev.w * i3;
        const __half2* __restrict__ hb = (const __half2*)g_Hh + (size_t)v * 128 + lane;
        const float2 h0 = __half22float2(hb[0]);
        const float2 h1 = __half22float2(hb[32]);
        const float2 h2 = __half22float2(hb[64]);
        const float2 h3 = __half22float2(hb[96]);
        ax += a0 * h0.x + a1 * h1.x + a2 * h2.x + a3 * h3.x;
        ay += a0 * h0.y + a1 * h1.y + a2 * h2.y + a3 * h3.y;
    }
    *(float2*)(out + (size_t)u * 64 + lane * 2) = make_float2(ax * 0.25f, ay * 0.25f);
}

// ---------------- launch ----------------
extern "C" void kernel_launch(void* const* d_in, const int* in_sizes, int n_in,
                              void* d_out, int out_size) {
    const float* x  = (const float*)d_in[0];
    const void*  ei = d_in[1];
    const float* Wq = (const float*)d_in[2];
    const float* Wk = (const float*)d_in[3];
    const float* Wh = (const float*)d_in[4];
    const float* bh = (const float*)d_in[5];
    float* out = (float*)d_out;

    const int n = in_sizes[0] / IN_DIM;
    const int E = in_sizes[1] / 2;
    const int nb = (n + 1023) / 1024;

    cudaFuncSetAttribute(gat_gemm, cudaFuncAttributeMaxDynamicSharedMemorySize, GEMM_SMEM);

    gat_detect<<<1, 32>>>(ei, E);
    gat_xh<<<(n * 64 + 255) / 256, 256>>>(x, n * 64, n);
    gat_wh<<<3, 256>>>(Wq, Wk, Wh);

    dim3 gg((n + BM - 1) / BM, 4);      // y<3: GEMM Q/K/H; y==3: deg count
    gat_gemm<<<gg, NT, GEMM_SMEM>>>(bh, ei, E, n);

    gat_scan1<<<nb, 1024>>>(n);
    gat_scan2<<<1, 128>>>(nb, n);
    gat_scan3<<<nb * 4, 256>>>(n);
    gat_scatter<<<(E + 255) / 256, 256>>>(ei, E);

    const int nblocks = (n * 32 + 255) / 256;
    gat_score<<<nblocks, 256>>>(n);
    gat_aggr<<<nblocks, 256>>>(out, n);
}

// round 17
// speedup vs baseline: 1.1201x; 1.1201x over previous
#include <cuda_runtime.h>
#include <cuda_fp16.h>
#include <cstdint>

#define N_NODES 100000
#define N_EDGES 1600000
#define IN_DIM 128
#define OUT_DIM 64
#define NEG 0.2f
#define EPSV 1e-8f

// ---------------- scratch (device globals: allocation-free) ----------------
__device__ __half g_Qh[(size_t)N_NODES * 256];   // leaky(Q) fp16
__device__ __half g_Kh[(size_t)N_NODES * 256];   // leaky(K) fp16
__device__ __half g_Hh[(size_t)N_NODES * 256];   // H + bias, fp16
__device__ __half g_xh[(size_t)N_NODES * 128];   // x in fp16
__device__ __half g_Wh[(size_t)3 * 256 * 128];   // W in fp16, [mtx][n][k]
__device__ float  g_e [(size_t)N_EDGES * 4];     // exp(score), [edge][head]
__device__ float  g_zinv[(size_t)N_NODES * 4];   // 1/(z+eps), [node][head]
__device__ int    g_ecol[N_EDGES];
__device__ int    g_deg [N_NODES];
__device__ int    g_rowptr[N_NODES + 1];
__device__ int    g_cursor[N_NODES];
__device__ int    g_bsum[128];
__device__ int    g_boff[128];
__device__ int    g_is64;

// ---------------- helpers ----------------
__device__ __forceinline__ void mma_f16(float* d, const uint32_t* a, uint32_t b0, uint32_t b1) {
    asm volatile(
        "mma.sync.aligned.m16n8k16.row.col.f32.f16.f16.f32 "
        "{%0,%1,%2,%3}, {%4,%5,%6,%7}, {%8,%9}, {%0,%1,%2,%3};"
        : "+f"(d[0]), "+f"(d[1]), "+f"(d[2]), "+f"(d[3])
        : "r"(a[0]), "r"(a[1]), "r"(a[2]), "r"(a[3]), "r"(b0), "r"(b1));
}
__device__ __forceinline__ void ldm4(uint32_t* r, uint32_t addr) {
    asm volatile("ldmatrix.sync.aligned.m8n8.x4.shared.b16 {%0,%1,%2,%3}, [%4];"
                 : "=r"(r[0]), "=r"(r[1]), "=r"(r[2]), "=r"(r[3]) : "r"(addr));
}
__device__ __forceinline__ void cp16(uint32_t smem_addr, const void* gptr, int srcsize) {
    asm volatile("cp.async.cg.shared.global [%0], [%1], 16, %2;"
                 :: "r"(smem_addr), "l"(gptr), "r"(srcsize) : "memory");
}
// dot of one fp16 K/Q 16-byte segment against 8 fp32 q values
__device__ __forceinline__ float dot8(const float* qv, uint4 kv) {
    const float2 k0 = __half22float2(*(const __half2*)&kv.x);
    const float2 k1 = __half22float2(*(const __half2*)&kv.y);
    const float2 k2 = __half22float2(*(const __half2*)&kv.z);
    const float2 k3 = __half22float2(*(const __half2*)&kv.w);
    return qv[0] * k0.x + qv[1] * k0.y + qv[2] * k1.x + qv[3] * k1.y
         + qv[4] * k2.x + qv[5] * k2.y + qv[6] * k3.x + qv[7] * k3.y;
}

// ---------------- dtype detection (int64 vs silently-int32 edge_index) -----
__global__ void gat_detect(const void* __restrict__ ei, int E) {
    if (threadIdx.x == 0 && blockIdx.x == 0) {
        const long long* p = (const long long*)ei;
        const int stride = E / 16;
        int ok = 1;
        #pragma unroll
        for (int i = 0; i < 16; i++) {
            long long v = p[(size_t)i * stride];
            if (v < 0 || v >= (long long)N_NODES) ok = 0;
        }
        g_is64 = ok;
    }
}

__device__ __forceinline__ int load_idx(const void* __restrict__ ei, int pos) {
    if (g_is64) return (int)((const long long*)ei)[pos];
    return ((const int*)ei)[pos];
}

// ---------------- fp16 conversions (+ fused deg zero) ----------------
__global__ void gat_xh(const float* __restrict__ x, int total2, int n) {
    const int i = blockIdx.x * blockDim.x + threadIdx.x;   // handles 2 floats
    if (i < total2) {
        const float2 v = *(const float2*)(x + (size_t)i * 2);
        *(__half2*)(g_xh + (size_t)i * 2) = __floats2half2_rn(v.x, v.y);
    }
    if (i < n) g_deg[i] = 0;
}
__global__ void gat_wh(const float* __restrict__ Wq, const float* __restrict__ Wk,
                       const float* __restrict__ Wh) {
    const float* __restrict__ W = (blockIdx.x == 0) ? Wq : ((blockIdx.x == 1) ? Wk : Wh);
    __half* __restrict__ dst = g_Wh + (size_t)blockIdx.x * 256 * 128;
    for (int i = threadIdx.x; i < 256 * 128 / 2; i += blockDim.x) {
        const float2 v = *(const float2*)(W + (size_t)i * 2);
        *(__half2*)(dst + (size_t)i * 2) = __floats2half2_rn(v.x, v.y);
    }
}

// ---------------- fp16 mma GEMM (CTA 64x256, warp tile 32x64) --------------
// gridDim = (ceil(n/64), 4): y<3 -> GEMM matrix y; y==3 -> deg count.
// Single K-chunk (BKH=128): one cp.async fill, one sync, 8 mma k-steps.
// LDH=136 halves (272 B row stride, ≡16 mod 128) -> ldmatrix conflict-free.
#define BM 64
#define LDH 136
#define GEMM_SMEM ((BM + 256) * LDH * 2)   // 87040 B

__global__ __launch_bounds__(256, 2) void gat_gemm(
    const float* __restrict__ bh, const void* __restrict__ ei, int E, int n)
{
    if (blockIdx.y == 3) {
        const int stride = gridDim.x * 256;
        for (int e = blockIdx.x * 256 + threadIdx.x; e < E; e += stride)
            atomicAdd(&g_deg[load_idx(ei, e)], 1);
        return;
    }

    extern __shared__ __half smem[];
    __half* As = smem;                 // BM x LDH
    __half* Bs = smem + BM * LDH;      // 256 x LDH

    const int tid  = threadIdx.x;
    const int wid  = tid >> 5;
    const int lane = tid & 31;
    const int m0   = blockIdx.x * BM;
    const int mtx  = blockIdx.y;                 // 0=Q, 1=K, 2=H
    const __half* __restrict__ Wp = g_Wh + (size_t)mtx * 256 * 128;

    const int wr = (wid >> 2) * 32;              // warp row base
    const int wc = (wid & 3) * 64;               // warp col base
    const int lr = lane >> 2;
    const int lc = lane & 3;

    const int sel = lane >> 3;
    const int rL  = (sel & 1) * 8 + (lane & 7);
    const int cL  = (sel >> 1) * 8;

    const uint32_t aBase = (uint32_t)__cvta_generic_to_shared(As);
    const uint32_t bBase = (uint32_t)__cvta_generic_to_shared(Bs);

    // fill A: 64 rows x 128 halves = 1024 16B-chunks; 4 per thread (cp.async)
    #pragma unroll
    for (int i = tid; i < 1024; i += 256) {
        const int row = i >> 4;                  // 16 chunks per row
        const int seg = (i & 15) * 8;            // halves
        const int grow = m0 + row;
        const int ok = (grow < n);
        const __half* gp = g_xh + (size_t)(ok ? grow : 0) * 128 + seg;
        cp16(aBase + (row * LDH + seg) * 2, gp, ok ? 16 : 0);   // srcsize 0 -> zero fill
    }
    // fill B: 256 rows x 128 halves = 4096 chunks; 16 per thread
    #pragma unroll
    for (int i = tid; i < 4096; i += 256) {
        const int row = i >> 4;
        const int seg = (i & 15) * 8;
        cp16(bBase + (row * LDH + seg) * 2, Wp + (size_t)row * 128 + seg, 16);
    }
    asm volatile("cp.async.commit_group;" ::: "memory");
    asm volatile("cp.async.wait_group 0;" ::: "memory");
    __syncthreads();

    uint32_t aAddr[2], bAddr[4];
    #pragma unroll
    for (int i = 0; i < 2; i++)
        aAddr[i] = aBase + ((wr + i * 16 + rL) * LDH + cL) * 2;
    #pragma unroll
    for (int j2 = 0; j2 < 4; j2++)
        bAddr[j2] = bBase + ((wc + j2 * 16 + rL) * LDH + cL) * 2;

    float acc[2][8][4];
    #pragma unroll
    for (int i = 0; i < 2; i++)
        #pragma unroll
        for (int j = 0; j < 8; j++)
            #pragma unroll
            for (int t = 0; t < 4; t++) acc[i][j][t] = 0.f;

    #pragma unroll
    for (int ks = 0; ks < 8; ks++) {
        const uint32_t ko = ks * 32;             // 16 halves = 32 B per k-step
        uint32_t a[2][4];
        ldm4(a[0], aAddr[0] + ko);
        ldm4(a[1], aAddr[1] + ko);
        #pragma unroll
        for (int j2 = 0; j2 < 4; j2++) {
            uint32_t b[4];
            ldm4(b, bAddr[j2] + ko);
            mma_f16(acc[0][2 * j2],     a[0], b[0], b[2]);
            mma_f16(acc[1][2 * j2],     a[1], b[0], b[2]);
            mma_f16(acc[0][2 * j2 + 1], a[0], b[1], b[3]);
            mma_f16(acc[1][2 * j2 + 1], a[1], b[1], b[3]);
        }
    }

    // epilogue: Q/K -> fp16 + leaky; H -> fp16 + bias
    __half* __restrict__ dsth = (mtx == 0) ? g_Qh : ((mtx == 1) ? g_Kh : g_Hh);
    #pragma unroll
    for (int i = 0; i < 2; i++) {
        const int r0 = m0 + wr + i * 16 + lr;
        const int r1 = r0 + 8;
        #pragma unroll
        for (int j = 0; j < 8; j++) {
            const int col = wc + j * 8 + lc * 2;
            float2 v0 = make_float2(acc[i][j][0], acc[i][j][1]);
            float2 v1 = make_float2(acc[i][j][2], acc[i][j][3]);
            if (mtx < 2) {
                v0.x = v0.x > 0.f ? v0.x : NEG * v0.x;
                v0.y = v0.y > 0.f ? v0.y : NEG * v0.y;
                v1.x = v1.x > 0.f ? v1.x : NEG * v1.x;
                v1.y = v1.y > 0.f ? v1.y : NEG * v1.y;
            } else {
                const float bx = bh[col], by = bh[col + 1];
                v0.x += bx; v0.y += by;
                v1.x += bx; v1.y += by;
            }
            if (r0 < n) *(__half2*)(dsth + (size_t)r0 * 256 + col) = __floats2half2_rn(v0.x, v0.y);
            if (r1 < n) *(__half2*)(dsth + (size_t)r1 * 256 + col) = __floats2half2_rn(v1.x, v1.y);
        }
    }
}

// ---------------- CSR build ----------------
__global__ void gat_scan1(int n) {
    __shared__ int warpsum[32];
    const int tid  = threadIdx.x;
    const int lane = tid & 31;
    const int wid  = tid >> 5;
    const int i = blockIdx.x * 1024 + tid;
    const int v = (i < n) ? g_deg[i] : 0;
    int s = v;
    #pragma unroll
    for (int off = 1; off < 32; off <<= 1) {
        int t = __shfl_up_sync(0xFFFFFFFFu, s, off);
        if (lane >= off) s += t;
    }
    if (lane == 31) warpsum[wid] = s;
    __syncthreads();
    if (wid == 0) {
        int w = warpsum[lane];
        #pragma unroll
        for (int off = 1; off < 32; off <<= 1) {
            int t = __shfl_up_sync(0xFFFFFFFFu, w, off);
            if (lane >= off) w += t;
        }
        warpsum[lane] = w;
    }
    __syncthreads();
    const int wbase = (wid == 0) ? 0 : warpsum[wid - 1];
    if (i < n) g_rowptr[i] = wbase + s - v;
    if (tid == 1023) g_bsum[blockIdx.x] = warpsum[31];
}

__global__ void gat_scan2(int nb, int n) {
    const int tid  = threadIdx.x;   // 128 threads
    const int lane = tid & 31;
    const int wid  = tid >> 5;
    __shared__ int warpsum[4];
    const int v = (tid < nb) ? g_bsum[tid] : 0;
    int s = v;
    #pragma unroll
    for (int off = 1; off < 32; off <<= 1) {
        int t = __shfl_up_sync(0xFFFFFFFFu, s, off);
        if (lane >= off) s += t;
    }
    if (lane == 31) warpsum[wid] = s;
    __syncthreads();
    int wbase = 0;
    #pragma unroll
    for (int w = 0; w < 4; w++) if (w < wid) wbase += warpsum[w];
    if (tid < nb) g_boff[tid] = wbase + s - v;
    if (tid == 127) g_rowptr[n] = wbase + s;
}

__global__ void gat_scan3(int n) {
    const int i = blockIdx.x * blockDim.x + threadIdx.x;
    if (i < n) {
        const int r = g_rowptr[i] + g_boff[blockIdx.x >> 2];
        g_rowptr[i] = r;
        g_cursor[i] = r;
    }
}

__global__ void gat_scatter(const void* __restrict__ ei, int E) {
    int e = blockIdx.x * blockDim.x + threadIdx.x;
    if (e < E) {
        int r = load_idx(ei, e);
        int c = load_idx(ei, E + e);
        int p = atomicAdd(&g_cursor[r], 1);
        g_ecol[p] = c;
    }
}

// ---------------- score pass (warp per node), 2-edge unrolled --------------
// K row = 512 bytes fp16. lane l loads uint4 (8 halves) at byte offset l*16.
// head h = l>>3, slot t = l&7 covers dims t*8..t*8+7.
__global__ __launch_bounds__(256) void gat_score(int n) {
    const int warp = (blockIdx.x * blockDim.x + threadIdx.x) >> 5;
    const int lane = threadIdx.x & 31;
    if (warp >= n) return;
    const int u = warp;
    const int h = lane >> 3;
    const int t = lane & 7;
    const int p0 = g_rowptr[u], p1 = g_rowptr[u + 1];

    float qv[8];
    {
        const uint4 q16 = *(const uint4*)((const char*)g_Qh + (size_t)u * 512 + lane * 16);
        const float2 a0 = __half22float2(*(const __half2*)&q16.x);
        const float2 a1 = __half22float2(*(const __half2*)&q16.y);
        const float2 a2 = __half22float2(*(const __half2*)&q16.z);
        const float2 a3 = __half22float2(*(const __half2*)&q16.w);
        qv[0] = a0.x; qv[1] = a0.y; qv[2] = a1.x; qv[3] = a1.y;
        qv[4] = a2.x; qv[5] = a2.y; qv[6] = a3.x; qv[7] = a3.y;
    }

    float z = 0.f;
    int p = p0;
    for (; p + 1 < p1; p += 2) {
        const int v0 = g_ecol[p];
        const int v1 = g_ecol[p + 1];
        const uint4 kv0 = *(const uint4*)((const char*)g_Kh + (size_t)v0 * 512 + lane * 16);
        const uint4 kv1 = *(const uint4*)((const char*)g_Kh + (size_t)v1 * 512 + lane * 16);
        float s0 = dot8(qv, kv0);
        float s1 = dot8(qv, kv1);
        s0 += __shfl_xor_sync(0xFFFFFFFFu, s0, 4);
        s1 += __shfl_xor_sync(0xFFFFFFFFu, s1, 4);
        s0 += __shfl_xor_sync(0xFFFFFFFFu, s0, 2);
        s1 += __shfl_xor_sync(0xFFFFFFFFu, s1, 2);
        s0 += __shfl_xor_sync(0xFFFFFFFFu, s0, 1);
        s1 += __shfl_xor_sync(0xFFFFFFFFu, s1, 1);
        const float e0 = __expf(s0 * 0.125f);
        const float e1 = __expf(s1 * 0.125f);
        z += e0 + e1;
        if (t == 0) {
            g_e[4 * (size_t)p + h] = e0;
            g_e[4 * (size_t)(p + 1) + h] = e1;
        }
    }
    if (p < p1) {
        const int v = g_ecol[p];
        const uint4 kv = *(const uint4*)((const char*)g_Kh + (size_t)v * 512 + lane * 16);
        float s = dot8(qv, kv);
        s += __shfl_xor_sync(0xFFFFFFFFu, s, 4);
        s += __shfl_xor_sync(0xFFFFFFFFu, s, 2);
        s += __shfl_xor_sync(0xFFFFFFFFu, s, 1);
        const float e = __expf(s * 0.125f);
        z += e;
        if (t == 0) g_e[4 * (size_t)p + h] = e;
    }
    if (t == 0) g_zinv[4 * (size_t)u + h] = 1.0f / (z + EPSV);
}

// ---------------- aggregate pass (warp per node), 2-edge unrolled ----------
// lane l handles out dims 2l, 2l+1: head h at half2 index h*32 + l of the row.
__global__ __launch_bounds__(256) void gat_aggr(float* __restrict__ out, int n) {
    const int warp = (blockIdx.x * blockDim.x + threadIdx.x) >> 5;
    const int lane = threadIdx.x & 31;
    if (warp >= n) return;
    const int u = warp;
    const int p0 = g_rowptr[u], p1 = g_rowptr[u + 1];

    const float4 zv = *(const float4*)(g_zinv + 4 * (size_t)u);
    const float i0 = zv.x, i1 = zv.y, i2 = zv.z, i3 = zv.w;

    float ax = 0.f, ay = 0.f;
    int p = p0;
    for (; p + 1 < p1; p += 2) {
        const int v0 = g_ecol[p];
        const int v1 = g_ecol[p + 1];
        const float4 ea = *(const float4*)(g_e + 4 * (size_t)p);
        const float4 eb = *(const float4*)(g_e + 4 * (size_t)(p + 1));
        const __half2* __restrict__ ha = (const __half2*)g_Hh + (size_t)v0 * 128 + lane;
        const __half2* __restrict__ hb = (const __half2*)g_Hh + (size_t)v1 * 128 + lane;
        const float2 a0 = __half22float2(ha[0]);
        const float2 a1 = __half22float2(ha[32]);
        const float2 a2 = __half22float2(ha[64]);
        const float2 a3 = __half22float2(ha[96]);
        const float2 b0 = __half22float2(hb[0]);
        const float2 b1 = __half22float2(hb[32]);
        const float2 b2 = __half22float2(hb[64]);
        const float2 b3 = __half22float2(hb[96]);
        const float wa0 = ea.x * i0, wa1 = ea.y * i1, wa2 = ea.z * i2, wa3 = ea.w * i3;
        const float wb0 = eb.x * i0, wb1 = eb.y * i1, wb2 = eb.z * i2, wb3 = eb.w * i3;
        ax += wa0 * a0.x + wa1 * a1.x + wa2 * a2.x + wa3 * a3.x
            + wb0 * b0.x + wb1 * b1.x + wb2 * b2.x + wb3 * b3.x;
        ay += wa0 * a0.y + wa1 * a1.y + wa2 * a2.y + wa3 * a3.y
            + wb0 * b0.y + wb1 * b1.y + wb2 * b2.y + wb3 * b3.y;
    }
    if (p < p1) {
        const int v = g_ecol[p];
        const float4 ev = *(const float4*)(g_e + 4 * (size_t)p);
        const __half2* __restrict__ hb = (const __half2*)g_Hh + (size_t)v * 128 + lane;
        const float2 h0 = __half22float2(hb[0]);
        const float2 h1 = __half22float2(hb[32]);
        const float2 h2 = __half22float2(hb[64]);
        const float2 h3 = __half22float2(hb[96]);
        const float a0 = ev.x * i0, a1 = ev.y * i1, a2 = ev.z * i2, a3 = ev.w * i3;
        ax += a0 * h0.x + a1 * h1.x + a2 * h2.x + a3 * h3.x;
        ay += a0 * h0.y + a1 * h1.y + a2 * h2.y + a3 * h3.y;
    }
    *(float2*)(out + (size_t)u * 64 + lane * 2) = make_float2(ax * 0.25f, ay * 0.25f);
}

// ---------------- launch ----------------
extern "C" void kernel_launch(void* const* d_in, const int* in_sizes, int n_in,
                              void* d_out, int out_size) {
    const float* x  = (const float*)d_in[0];
    const void*  ei = d_in[1];
    const float* Wq = (const float*)d_in[2];
    const float* Wk = (const float*)d_in[3];
    const float* Wh = (const float*)d_in[4];
    const float* bh = (const float*)d_in[5];
    float* out = (float*)d_out;

    const int n = in_sizes[0] / IN_DIM;
    const int E = in_sizes[1] / 2;
    const int nb = (n + 1023) / 1024;

    cudaFuncSetAttribute(gat_gemm, cudaFuncAttributeMaxDynamicSharedMemorySize, GEMM_SMEM);

    gat_detect<<<1, 32>>>(ei, E);
    gat_xh<<<(n * 64 + 255) / 256, 256>>>(x, n * 64, n);
    gat_wh<<<3, 256>>>(Wq, Wk, Wh);

    dim3 gg((n + BM - 1) / BM, 4);      // y<3: GEMM Q/K/H; y==3: deg count
    gat_gemm<<<gg, 256, GEMM_SMEM>>>(bh, ei, E, n);

    gat_scan1<<<nb, 1024>>>(n);
    gat_scan2<<<1, 128>>>(nb, n);
    gat_scan3<<<nb * 4, 256>>>(n);
    gat_scatter<<<(E + 255) / 256, 256>>>(ei, E);

    const int nblocks = (n * 32 + 255) / 256;
    gat_score<<<nblocks, 256>>>(n);
    gat_aggr<<<nblocks, 256>>>(out, n);
}